// round 13
// baseline (speedup 1.0000x reference)
#include <cuda_runtime.h>
#include <cuda_bf16.h>
#include <cstdint>

#define Bsz  8
#define Tlen 1024
#define Hd   1024
#define NG   6144   // fused fwd+rev gate width: [f|o|z]fwd [f|o|z]rev

// ---------------- device scratch (no allocation allowed) -------------------
__device__ float          g_gates[(size_t)Bsz * Tlen * NG];        // 201 MB
__device__ __nv_bfloat16  g_xhi [(size_t)Bsz * Tlen * 1024];
__device__ __nv_bfloat16  g_xlo [(size_t)Bsz * Tlen * 1024];
__device__ __nv_bfloat16  g_o0hi[(size_t)Bsz * Tlen * 2048];
__device__ __nv_bfloat16  g_o0lo[(size_t)Bsz * Tlen * 2048];
__device__ __nv_bfloat16  g_wbhi[(size_t)6144 * NG];   // k-major bf16 [3C][6144]
__device__ __nv_bfloat16  g_wblo[(size_t)6144 * NG];

// ---------------------------------------------------------------------------
__device__ __forceinline__ void split2(float a, float b, uint32_t& hp, uint32_t& lp)
{
    __nv_bfloat16 ha = __float2bfloat16(a), hb = __float2bfloat16(b);
    float la = a - __bfloat162float(ha);
    float lb = b - __bfloat162float(hb);
    __nv_bfloat162 hv; hv.x = ha; hv.y = hb;
    __nv_bfloat162 lv; lv.x = __float2bfloat16(la); lv.y = __float2bfloat16(lb);
    hp = *(uint32_t*)&hv; lp = *(uint32_t*)&lv;
}

__global__ void prep_x(const float4* __restrict__ x,
                       uint32_t* __restrict__ hi, uint32_t* __restrict__ lo)
{
    int i = blockIdx.x * blockDim.x + threadIdx.x;
    float4 v = x[i];
    uint32_t h0, l0, h1, l1;
    split2(v.x, v.y, h0, l0);
    split2(v.z, v.w, h1, l1);
    ((uint2*)hi)[i] = make_uint2(h0, h1);
    ((uint2*)lo)[i] = make_uint2(l0, l1);
}

// weight prep: w [3072, C, 3] fp32 -> hi/lo bf16 planes [3C][6144], k-major
__global__ void prep_w(const float* __restrict__ w,
                       __nv_bfloat16* __restrict__ wbhi,
                       __nv_bfloat16* __restrict__ wblo,
                       int C, int colbase)
{
    __shared__ float sm[32][97];
    const int tid = threadIdx.x;
    const int cb = blockIdx.x;
    const int jb = blockIdx.y;

    for (int i = tid; i < 32 * 96; i += 256) {
        int j = i / 96, q = i % 96;
        sm[j][q] = w[(size_t)(jb * 32 + j) * 3 * C + cb * 96 + q];
    }
    __syncthreads();

    for (int i = tid; i < 1536; i += 256) {
        int jp = i & 15;
        int tap = (i >> 4) % 3;
        int cl  = i / 48;
        int q   = cl * 3 + tap;
        uint32_t hp, lp;
        split2(sm[jp * 2][q], sm[jp * 2 + 1][q], hp, lp);
        size_t r = (size_t)tap * C + cb * 32 + cl;
        size_t off = r * NG + colbase + jb * 32 + jp * 2;
        *(uint32_t*)&wbhi[off] = hp;
        *(uint32_t*)&wblo[off] = lp;
    }
}

// ---------------------------------------------------------------------------
__device__ __forceinline__ void cp_async16(uint32_t smem, const void* gmem, int bytes)
{
    asm volatile("cp.async.cg.shared.global [%0], [%1], 16, %2;\n"
                 :: "r"(smem), "l"(gmem), "r"(bytes));
}
__device__ __forceinline__ void cp_commit()
{
    asm volatile("cp.async.commit_group;\n" ::: "memory");
}
template <int N>
__device__ __forceinline__ void cp_wait()
{
    asm volatile("cp.async.wait_group %0;\n" :: "n"(N) : "memory");
}

#define MMA_BF16(acc, a, b0, b1)                                              \
    asm volatile("mma.sync.aligned.m16n8k16.row.col.f32.bf16.bf16.f32 "       \
                 "{%0,%1,%2,%3}, {%4,%5,%6,%7}, {%8,%9}, {%0,%1,%2,%3};\n"    \
                 : "+f"(acc[0]), "+f"(acc[1]), "+f"(acc[2]), "+f"(acc[3])     \
                 : "r"(a[0]), "r"(a[1]), "r"(a[2]), "r"(a[3]),                \
                   "r"(b0), "r"(b1));

#define LDSM_X4(r, addr)                                                      \
    asm volatile("ldmatrix.sync.aligned.m8n8.x4.shared.b16 "                  \
                 "{%0,%1,%2,%3}, [%4];"                                       \
                 : "=r"((r)[0]), "=r"((r)[1]), "=r"((r)[2]), "=r"((r)[3])     \
                 : "r"(addr));

#define LDSM_X4T(r, addr)                                                     \
    asm volatile("ldmatrix.sync.aligned.m8n8.x4.trans.shared.b16 "            \
                 "{%0,%1,%2,%3}, [%4];"                                       \
                 : "=r"((r)[0]), "=r"((r)[1]), "=r"((r)[2]), "=r"((r)[3])     \
                 : "r"(addr));

// ---------------------------------------------------------------------------
// bf16x3 conv-as-GEMM (round-12 champion + hoisted loader pointers):
// BM=128 BN=64, 256 threads (4m x 2n warps, warp tile 32x32), 2 CTAs/SM.
// 4-stage cp.async ring, register fragment double buffering.
// Loader: per-thread base pointers hoisted; per stage only +kt*32 (A) and
// +kt*32*NG (B) remain. Boundary predicates precomputed per tap.
// Swizzles: A chunk ^ ((row>>1)&3), B chunk ^ (row&7).
// ---------------------------------------------------------------------------
// stage layout (bytes): Ahi 8192 | Alo 8192 | Bhi 4096 | Blo 4096 = 24576
#define STG_SZ   24576
#define STG_ALO  8192
#define STG_BHI  16384
#define STG_BLO  20480
#define SMEM_TOTAL (4 * STG_SZ)

template <int C>
__global__ void __launch_bounds__(256, 2) conv_gemm(
    const __nv_bfloat16* __restrict__ Ahi,
    const __nv_bfloat16* __restrict__ Alo,
    const __nv_bfloat16* __restrict__ Bhi_,
    const __nv_bfloat16* __restrict__ Blo_,
    const float* __restrict__ biasF,
    const float* __restrict__ biasR,
    float* __restrict__ gates)
{
    extern __shared__ char smraw[];

    const int tid  = threadIdx.x;          // 0..255
    const int lane = tid & 31;
    const int warp = tid >> 5;             // 0..7
    const int wm   = warp & 3;             // M
    const int wn   = warp >> 2;            // N (0..1)
    const int gp   = lane >> 2;
    const int tg   = lane & 3;
    const int lr   = lane & 15;
    const int lh   = lane >> 4;

    const int row0 = blockIdx.y << 7;
    const int col0 = blockIdx.x << 6;      // BN=64
    const int t0   = row0 & (Tlen - 1);
    const __nv_bfloat16* Ahb = Ahi + (size_t)(row0 - t0) * C;

    constexpr int KTT = C / 32;            // k-tiles per tap
    const int NKt = 3 * KTT;

    float acc[2][4][4];
#pragma unroll
    for (int a = 0; a < 2; a++)
#pragma unroll
        for (int b = 0; b < 4; b++)
#pragma unroll
            for (int c = 0; c < 4; c++) acc[a][b][c] = 0.f;

    uint32_t sbase;
    asm("{ .reg .u64 t; cvta.to.shared.u64 t, %1; cvt.u32.u64 %0, t; }"
        : "=r"(sbase) : "l"(smraw));

    // ---- hoisted loader state (per-thread constants) ----
    const ptrdiff_t dALo = Alo - Ahi;      // plane deltas (uniform)
    const ptrdiff_t dBLo = Blo_ - Bhi_;
    const int arow = tid >> 2;             // A row (r=0); r=1 adds 64
    const int ac   = tid & 3;              // A chunk
    const int tt0 = t0 + arow, tt1 = tt0 + 64;
    const int okt0_0 = (tt0 > 0),    okt0_1 = (tt1 > 0);
    const int okt2_0 = (tt0 < 1023), okt2_1 = (tt1 < 1023);
    const __nv_bfloat16* aB0 = Ahb + (size_t)(tt0 - 1) * C + ac * 8;
    const __nv_bfloat16* aB1 = Ahb + (size_t)(tt1 - 1) * C + ac * 8;
    const uint32_t dstA0 = (uint32_t)(arow * 64 + (ac ^ ((arow >> 1) & 3)) * 16);
    const uint32_t dstA1 = (uint32_t)((arow + 64) * 64 +
                                      (ac ^ (((arow + 64) >> 1) & 3)) * 16);
    const int brow = tid >> 3, bc = tid & 7;
    const __nv_bfloat16* bB = Bhi_ + (size_t)brow * NG + col0 + bc * 8;
    const uint32_t dstB = (uint32_t)(brow * 128 + (bc ^ (brow & 7)) * 16);

    auto load_stage = [&](int kt, uint32_t stb, int oa0, int oa1) {
        const __nv_bfloat16* s0 = aB0 + (size_t)kt * 32;
        const __nv_bfloat16* s1 = aB1 + (size_t)kt * 32;
        if (!oa0) s0 = Ahb;
        if (!oa1) s1 = Ahb;
        cp_async16(stb + dstA0,           s0,        oa0 ? 16 : 0);
        cp_async16(stb + dstA0 + STG_ALO, s0 + dALo, oa0 ? 16 : 0);
        cp_async16(stb + dstA1,           s1,        oa1 ? 16 : 0);
        cp_async16(stb + dstA1 + STG_ALO, s1 + dALo, oa1 ? 16 : 0);
        const __nv_bfloat16* bs = bB + (size_t)kt * (32 * NG);
        cp_async16(stb + STG_BHI + dstB, bs,        16);
        cp_async16(stb + STG_BLO + dstB, bs + dBLo, 16);
    };

    // ---- fragment buffers (double-buffered) ----
    uint32_t ahf[2][2][4], alf[2][2][4], bhf[2][8], blf[2][8];

    const uint32_t a_row_off  = (uint32_t)((wm * 32 + lr) * 64);
    const uint32_t a_chunk[2] = {
        (uint32_t)(((0 * 2 + lh) ^ ((lr >> 1) & 3)) * 16),
        (uint32_t)(((1 * 2 + lh) ^ ((lr >> 1) & 3)) * 16) };
    const uint32_t b_row_off  = (uint32_t)(lr * 128);
    const uint32_t b_chunk[2] = {
        (uint32_t)(((wn * 4 + 0 * 2 + lh) ^ (lr & 7)) * 16),
        (uint32_t)(((wn * 4 + 1 * 2 + lh) ^ (lr & 7)) * 16) };

    auto load_frags = [&](int buf, int st_idx, int ks) {
        const uint32_t st = sbase + st_idx * STG_SZ;
        uint32_t aaddr = st + a_row_off + a_chunk[ks];
        LDSM_X4(ahf[buf][0], aaddr);
        LDSM_X4(ahf[buf][1], aaddr + 1024);            // +16 rows * 64B
        LDSM_X4(alf[buf][0], aaddr + STG_ALO);
        LDSM_X4(alf[buf][1], aaddr + STG_ALO + 1024);
        uint32_t bbase = st + STG_BHI + (uint32_t)(ks * 2048) + b_row_off;
#pragma unroll
        for (int np = 0; np < 2; np++) {
            uint32_t baddr = bbase + b_chunk[np];
            LDSM_X4T(&bhf[buf][np * 4], baddr);
            LDSM_X4T(&blf[buf][np * 4], baddr + (STG_BLO - STG_BHI));
        }
    };

    auto mma_all = [&](int buf) {
        // term 1: lo*hi — 8 independent MMAs
#pragma unroll
        for (int ni = 0; ni < 4; ni++) {
            MMA_BF16(acc[0][ni], alf[buf][0], bhf[buf][ni * 2], bhf[buf][ni * 2 + 1]);
            MMA_BF16(acc[1][ni], alf[buf][1], bhf[buf][ni * 2], bhf[buf][ni * 2 + 1]);
        }
        // term 2: hi*lo
#pragma unroll
        for (int ni = 0; ni < 4; ni++) {
            MMA_BF16(acc[0][ni], ahf[buf][0], blf[buf][ni * 2], blf[buf][ni * 2 + 1]);
            MMA_BF16(acc[1][ni], ahf[buf][1], blf[buf][ni * 2], blf[buf][ni * 2 + 1]);
        }
        // term 3: hi*hi
#pragma unroll
        for (int ni = 0; ni < 4; ni++) {
            MMA_BF16(acc[0][ni], ahf[buf][0], bhf[buf][ni * 2], bhf[buf][ni * 2 + 1]);
            MMA_BF16(acc[1][ni], ahf[buf][1], bhf[buf][ni * 2], bhf[buf][ni * 2 + 1]);
        }
    };

    // ---- prologue: stages 0,1,2 (all tap 0 since KTT >= 32) ----
    load_stage(0, sbase,              okt0_0, okt0_1); cp_commit();
    load_stage(1, sbase + STG_SZ,     okt0_0, okt0_1); cp_commit();
    load_stage(2, sbase + 2 * STG_SZ, okt0_0, okt0_1); cp_commit();
    cp_wait<1>();          // groups 0,1 arrived (group 2 may pend)
    __syncthreads();       // stages 0,1 visible
    load_frags(0, 0, 0);   // preload (tile 0, ks=0)

    // ---- main loop, 4x unrolled: stage of tile kt is kt&3 = u ----
    for (int base = 0; base < NKt; base += 4) {
#pragma unroll
        for (int u = 0; u < 4; u++) {
            const int kt = base + u;
            if (kt > 0) {
                cp_wait<1>();      // stages <= kt+1 arrived
                __syncthreads();   // visible; stage kt-1 fully consumed
            }
            // ks=0: prefetch (kt, ks=1) into buf 1; compute buf 0
            load_frags(1, u, 1);
            mma_all(0);
            // issue next stage's bulk loads while tensor pipe drains
            if (kt + 3 < NKt) {
                const int k3 = kt + 3;
                const int tap = (k3 >= KTT) + (k3 >= 2 * KTT);
                const int oa0 = (tap == 1) ? 1
                              : ((tap == 0) ? okt0_0 : okt2_0);
                const int oa1 = (tap == 1) ? 1
                              : ((tap == 0) ? okt0_1 : okt2_1);
                load_stage(k3, sbase + (((u + 3) & 3) * STG_SZ), oa0, oa1);
            }
            cp_commit();           // one group per tile (possibly empty)
            // ks=1: prefetch (kt+1, ks=0) into buf 0; compute buf 1
            if (kt + 1 < NKt) load_frags(0, (u + 1) & 3, 0);
            mma_all(1);
        }
    }

    // ---- epilogue: bias + activation (per-column act select) ----
    const int  dircol = (col0 >= 3072) ? 1 : 0;
    const float* bias = dircol ? biasR : biasF;
    const int  lcol0  = col0 - dircol * 3072;

#pragma unroll
    for (int mi = 0; mi < 2; mi++) {
        int r0g = row0 + wm * 32 + mi * 16 + gp;
#pragma unroll
        for (int ni = 0; ni < 4; ni++) {
            int cl  = lcol0 + wn * 32 + ni * 8 + tg * 2;   // bias/act index
            int cg  = col0  + wn * 32 + ni * 8 + tg * 2;   // global gate col
            const bool ztan = (cl >= 2048);                // z section -> tanh
            float b0v = bias[cl], b1v = bias[cl + 1];
            float v[4] = { acc[mi][ni][0] + b0v, acc[mi][ni][1] + b1v,
                           acc[mi][ni][2] + b0v, acc[mi][ni][3] + b1v };
#pragma unroll
            for (int j = 0; j < 4; j++) {
                if (ztan) v[j] = 1.f - __fdividef(2.f, __expf(2.f * v[j]) + 1.f);
                else      v[j] = __fdividef(1.f, 1.f + __expf(-v[j]));
            }
            *(float2*)(gates + (size_t)r0g * NG + cg)       = make_float2(v[0], v[1]);
            *(float2*)(gates + (size_t)(r0g + 8) * NG + cg) = make_float2(v[2], v[3]);
        }
    }
}

// ---------------------------------------------------------------------------
// fo-pool scan, both directions via blockIdx.y. 16x unrolled time loop
// (48 loads in flight per thread -> 2x MLP vs 8x unroll; scan is
// latency-bound at ~3.5 warps/SM).
// ---------------------------------------------------------------------------
template <bool L0>
__global__ void scan2(const float* __restrict__ gates,
                      float* __restrict__ out_f32,
                      __nv_bfloat16* __restrict__ ohi,
                      __nv_bfloat16* __restrict__ olo,
                      float* __restrict__ hid,
                      float* __restrict__ cel)
{
    const int dir = blockIdx.y;
    const int gid = blockIdx.x * blockDim.x + threadIdx.x;
    const int b = gid >> 10, h = gid & 1023;
    const float* gb = gates + (size_t)b * Tlen * NG + dir * 3072 + h;
    const size_t obase = (size_t)b * Tlen * 2048 + dir * 1024 + h;
    float c = 0.f;

    auto emit = [&](int t, float hv) {
        size_t idx = obase + (size_t)t * 2048;
        if (L0) {
            __nv_bfloat16 hh = __float2bfloat16(hv);
            ohi[idx] = hh;
            olo[idx] = __float2bfloat16(hv - __bfloat162float(hh));
        } else {
            out_f32[idx] = hv;
        }
    };

    if (dir == 0) {
        float hl = 0.f;
        for (int tt = 0; tt < Tlen; tt += 16) {
            float fv[16], ov[16], zv[16];
#pragma unroll
            for (int i = 0; i < 16; i++) {
                size_t o_ = (size_t)(tt + i) * NG;
                fv[i] = gb[o_]; ov[i] = gb[o_ + 1024]; zv[i] = gb[o_ + 2048];
            }
#pragma unroll
            for (int i = 0; i < 16; i++) {
                c = fmaf(fv[i], c - zv[i], zv[i]);
                hl = c * ov[i];
                emit(tt + i, hl);
            }
        }
        hid[b * 2048 + h] = hl;
        cel[b * 2048 + h] = c;
    } else {
        float cfirst = 0.f, hfirst = 0.f;
        for (int tt = Tlen - 16; tt >= 0; tt -= 16) {
            float fv[16], ov[16], zv[16];
#pragma unroll
            for (int i = 0; i < 16; i++) {
                size_t o_ = (size_t)(tt + i) * NG;
                fv[i] = gb[o_]; ov[i] = gb[o_ + 1024]; zv[i] = gb[o_ + 2048];
            }
#pragma unroll
            for (int i = 15; i >= 0; i--) {
                c = fmaf(fv[i], c - zv[i], zv[i]);
                float hv = c * ov[i];
                emit(tt + i, hv);
                if (tt + i == Tlen - 1) { cfirst = c; hfirst = hv; }
            }
        }
        hid[1024 + b * 2048 + h] = hfirst;
        cel[1024 + b * 2048 + h] = cfirst;
    }
}

// ---------------------------------------------------------------------------
extern "C" void kernel_launch(void* const* d_in, const int* in_sizes, int n_in,
                              void* d_out, int out_size)
{
    const float* x   = (const float*)d_in[0];
    const float* w0f = (const float*)d_in[2];
    const float* b0f = (const float*)d_in[3];
    const float* w0r = (const float*)d_in[4];
    const float* b0r = (const float*)d_in[5];
    const float* w1f = (const float*)d_in[6];
    const float* b1f = (const float*)d_in[7];
    const float* w1r = (const float*)d_in[8];
    const float* b1r = (const float*)d_in[9];

    float* out1 = (float*)d_out;                         // [B,T,2H]
    float* hid  = out1 + (size_t)Bsz * Tlen * 2 * Hd;    // [4,B,H]
    float* cel  = hid + 4 * Bsz * Hd;

    float *gates; __nv_bfloat16 *xhi, *xlo, *o0hi, *o0lo, *wbhi, *wblo;
    cudaGetSymbolAddress((void**)&gates, g_gates);
    cudaGetSymbolAddress((void**)&xhi,  g_xhi);
    cudaGetSymbolAddress((void**)&xlo,  g_xlo);
    cudaGetSymbolAddress((void**)&o0hi, g_o0hi);
    cudaGetSymbolAddress((void**)&o0lo, g_o0lo);
    cudaGetSymbolAddress((void**)&wbhi, g_wbhi);
    cudaGetSymbolAddress((void**)&wblo, g_wblo);

    cudaFuncSetAttribute(conv_gemm<1024>,
                         cudaFuncAttributeMaxDynamicSharedMemorySize, SMEM_TOTAL);
    cudaFuncSetAttribute(conv_gemm<2048>,
                         cudaFuncAttributeMaxDynamicSharedMemorySize, SMEM_TOTAL);

    // ---- layer 0 ----
    prep_x<<<8192, 256>>>((const float4*)x, (uint32_t*)xhi, (uint32_t*)xlo);
    prep_w<<<dim3(32, 96), 256>>>(w0f, wbhi, wblo, 1024, 0);
    prep_w<<<dim3(32, 96), 256>>>(w0r, wbhi, wblo, 1024, 3072);
    conv_gemm<1024><<<dim3(96, 64), 256, SMEM_TOTAL>>>(xhi, xlo, wbhi, wblo,
                                                       b0f, b0r, gates);
    scan2<true><<<dim3(32, 2), 256>>>(gates, nullptr, o0hi, o0lo, hid, cel);
    // ---- layer 1 ----
    prep_w<<<dim3(64, 96), 256>>>(w1f, wbhi, wblo, 2048, 0);
    prep_w<<<dim3(64, 96), 256>>>(w1r, wbhi, wblo, 2048, 3072);
    conv_gemm<2048><<<dim3(96, 64), 256, SMEM_TOTAL>>>(o0hi, o0lo, wbhi, wblo,
                                                       b1f, b1r, gates);
    scan2<false><<<dim3(32, 2), 256>>>(gates, out1, nullptr, nullptr,
                                       hid + 16384, cel + 16384);
}

// round 14
// speedup vs baseline: 1.1012x; 1.1012x over previous
#include <cuda_runtime.h>
#include <cuda_bf16.h>
#include <cstdint>

#define Bsz  8
#define Tlen 1024
#define Hd   1024
#define NG   6144   // fused fwd+rev gate width: [f|o|z]fwd [f|o|z]rev
#define NCK  16     // scan chunks per sequence
#define CKL  64     // chunk length

// ---------------- device scratch (no allocation allowed) -------------------
__device__ float          g_gates[(size_t)Bsz * Tlen * NG];        // 201 MB
__device__ __nv_bfloat16  g_xhi [(size_t)Bsz * Tlen * 1024];
__device__ __nv_bfloat16  g_xlo [(size_t)Bsz * Tlen * 1024];
__device__ __nv_bfloat16  g_o0hi[(size_t)Bsz * Tlen * 2048];
__device__ __nv_bfloat16  g_o0lo[(size_t)Bsz * Tlen * 2048];
__device__ __nv_bfloat16  g_wbhi[(size_t)6144 * NG];   // k-major bf16 [3C][6144]
__device__ __nv_bfloat16  g_wblo[(size_t)6144 * NG];
__device__ float          g_scA[2 * NCK * 8192];       // chunk products
__device__ float          g_scB[2 * NCK * 8192];       // chunk offsets

// ---------------------------------------------------------------------------
__device__ __forceinline__ void split2(float a, float b, uint32_t& hp, uint32_t& lp)
{
    __nv_bfloat16 ha = __float2bfloat16(a), hb = __float2bfloat16(b);
    float la = a - __bfloat162float(ha);
    float lb = b - __bfloat162float(hb);
    __nv_bfloat162 hv; hv.x = ha; hv.y = hb;
    __nv_bfloat162 lv; lv.x = __float2bfloat16(la); lv.y = __float2bfloat16(lb);
    hp = *(uint32_t*)&hv; lp = *(uint32_t*)&lv;
}

__global__ void prep_x(const float4* __restrict__ x,
                       uint32_t* __restrict__ hi, uint32_t* __restrict__ lo)
{
    int i = blockIdx.x * blockDim.x + threadIdx.x;
    float4 v = x[i];
    uint32_t h0, l0, h1, l1;
    split2(v.x, v.y, h0, l0);
    split2(v.z, v.w, h1, l1);
    ((uint2*)hi)[i] = make_uint2(h0, h1);
    ((uint2*)lo)[i] = make_uint2(l0, l1);
}

// weight prep: w [3072, C, 3] fp32 -> hi/lo bf16 planes [3C][6144], k-major
__global__ void prep_w(const float* __restrict__ w,
                       __nv_bfloat16* __restrict__ wbhi,
                       __nv_bfloat16* __restrict__ wblo,
                       int C, int colbase)
{
    __shared__ float sm[32][97];
    const int tid = threadIdx.x;
    const int cb = blockIdx.x;
    const int jb = blockIdx.y;

    for (int i = tid; i < 32 * 96; i += 256) {
        int j = i / 96, q = i % 96;
        sm[j][q] = w[(size_t)(jb * 32 + j) * 3 * C + cb * 96 + q];
    }
    __syncthreads();

    for (int i = tid; i < 1536; i += 256) {
        int jp = i & 15;
        int tap = (i >> 4) % 3;
        int cl  = i / 48;
        int q   = cl * 3 + tap;
        uint32_t hp, lp;
        split2(sm[jp * 2][q], sm[jp * 2 + 1][q], hp, lp);
        size_t r = (size_t)tap * C + cb * 32 + cl;
        size_t off = r * NG + colbase + jb * 32 + jp * 2;
        *(uint32_t*)&wbhi[off] = hp;
        *(uint32_t*)&wblo[off] = lp;
    }
}

// ---------------------------------------------------------------------------
__device__ __forceinline__ void cp_async16(uint32_t smem, const void* gmem, int bytes)
{
    asm volatile("cp.async.cg.shared.global [%0], [%1], 16, %2;\n"
                 :: "r"(smem), "l"(gmem), "r"(bytes));
}
__device__ __forceinline__ void cp_commit()
{
    asm volatile("cp.async.commit_group;\n" ::: "memory");
}
template <int N>
__device__ __forceinline__ void cp_wait()
{
    asm volatile("cp.async.wait_group %0;\n" :: "n"(N) : "memory");
}

#define MMA_BF16(acc, a, b0, b1)                                              \
    asm volatile("mma.sync.aligned.m16n8k16.row.col.f32.bf16.bf16.f32 "       \
                 "{%0,%1,%2,%3}, {%4,%5,%6,%7}, {%8,%9}, {%0,%1,%2,%3};\n"    \
                 : "+f"(acc[0]), "+f"(acc[1]), "+f"(acc[2]), "+f"(acc[3])     \
                 : "r"(a[0]), "r"(a[1]), "r"(a[2]), "r"(a[3]),                \
                   "r"(b0), "r"(b1));

#define LDSM_X4(r, addr)                                                      \
    asm volatile("ldmatrix.sync.aligned.m8n8.x4.shared.b16 "                  \
                 "{%0,%1,%2,%3}, [%4];"                                       \
                 : "=r"((r)[0]), "=r"((r)[1]), "=r"((r)[2]), "=r"((r)[3])     \
                 : "r"(addr));

#define LDSM_X4T(r, addr)                                                     \
    asm volatile("ldmatrix.sync.aligned.m8n8.x4.trans.shared.b16 "            \
                 "{%0,%1,%2,%3}, [%4];"                                       \
                 : "=r"((r)[0]), "=r"((r)[1]), "=r"((r)[2]), "=r"((r)[3])     \
                 : "r"(addr));

// ---------------------------------------------------------------------------
// bf16x3 conv-as-GEMM — ROUND-12 CHAMPION, VERBATIM (tensor 84.1%):
// BM=128 BN=64, 256 threads (4m x 2n warps, warp tile 32x32), 2 CTAs/SM.
// 4-stage cp.async ring, register fragment double buffering,
// tap-independent linear A addressing, 4x-unrolled kt loop.
// Swizzles: A chunk ^ ((row>>1)&3), B chunk ^ (row&7).
// ---------------------------------------------------------------------------
// stage layout (bytes): Ahi 8192 | Alo 8192 | Bhi 4096 | Blo 4096 = 24576
#define STG_SZ   24576
#define STG_ALO  8192
#define STG_BHI  16384
#define STG_BLO  20480
#define SMEM_TOTAL (4 * STG_SZ)

template <int C>
__global__ void __launch_bounds__(256, 2) conv_gemm(
    const __nv_bfloat16* __restrict__ Ahi,
    const __nv_bfloat16* __restrict__ Alo,
    const __nv_bfloat16* __restrict__ Bhi_,
    const __nv_bfloat16* __restrict__ Blo_,
    const float* __restrict__ biasF,
    const float* __restrict__ biasR,
    float* __restrict__ gates)
{
    extern __shared__ char smraw[];

    const int tid  = threadIdx.x;          // 0..255
    const int lane = tid & 31;
    const int warp = tid >> 5;             // 0..7
    const int wm   = warp & 3;             // M
    const int wn   = warp >> 2;            // N (0..1)
    const int gp   = lane >> 2;
    const int tg   = lane & 3;
    const int lr   = lane & 15;
    const int lh   = lane >> 4;

    const int row0 = blockIdx.y << 7;
    const int col0 = blockIdx.x << 6;      // BN=64
    const int t0   = row0 & (Tlen - 1);
    const __nv_bfloat16* Ahb = Ahi + (size_t)(row0 - t0) * C;

    constexpr int KTT = C / 32;            // k-tiles per tap
    const int NKt = 3 * KTT;

    float acc[2][4][4];
#pragma unroll
    for (int a = 0; a < 2; a++)
#pragma unroll
        for (int b = 0; b < 4; b++)
#pragma unroll
            for (int c = 0; c < 4; c++) acc[a][b][c] = 0.f;

    uint32_t sbase;
    asm("{ .reg .u64 t; cvta.to.shared.u64 t, %1; cvt.u32.u64 %0, t; }"
        : "=r"(sbase) : "l"(smraw));

    const ptrdiff_t dALo = Alo - Ahi;      // plane delta (uniform)
    const ptrdiff_t dBLo = Blo_ - Bhi_;
    const int tt0 = t0 + (tid >> 2);           // r=0 row
    const int tt1 = tt0 + 64;                  // r=1 row
    const int okt0_0 = (tt0 > 0),    okt0_1 = (tt1 > 0);
    const int okt2_0 = (tt0 < 1023), okt2_1 = (tt1 < 1023);

    auto load_stage = [&](int kt, uint32_t stb, int oa0, int oa1) {
#pragma unroll
        for (int r = 0; r < 2; r++) {
            int idx = tid + (r << 8);
            int row = idx >> 2, c = idx & 3;
            int ok  = r ? oa1 : oa0;
            const __nv_bfloat16* src =
                Ahb + (size_t)(t0 + row - 1) * C + (size_t)kt * 32 + c * 8;
            if (!ok) src = Ahb;            // any valid address; bytes=0
            uint32_t dst = stb + (uint32_t)(row * 64 +
                                            (c ^ ((row >> 1) & 3)) * 16);
            cp_async16(dst,           src,        ok ? 16 : 0);
            cp_async16(dst + STG_ALO, src + dALo, ok ? 16 : 0);
        }
        {
            int rowb = tid >> 3, cb = tid & 7;
            const __nv_bfloat16* bs =
                Bhi_ + (size_t)(kt * 32 + rowb) * NG + col0 + cb * 8;
            uint32_t dst = stb + STG_BHI +
                           (uint32_t)(rowb * 128 + (cb ^ (rowb & 7)) * 16);
            cp_async16(dst,                       bs,        16);
            cp_async16(dst + (STG_BLO - STG_BHI), bs + dBLo, 16);
        }
    };

    uint32_t ahf[2][2][4], alf[2][2][4], bhf[2][8], blf[2][8];

    const uint32_t a_row_off  = (uint32_t)((wm * 32 + lr) * 64);
    const uint32_t a_chunk[2] = {
        (uint32_t)(((0 * 2 + lh) ^ ((lr >> 1) & 3)) * 16),
        (uint32_t)(((1 * 2 + lh) ^ ((lr >> 1) & 3)) * 16) };
    const uint32_t b_row_off  = (uint32_t)(lr * 128);
    const uint32_t b_chunk[2] = {
        (uint32_t)(((wn * 4 + 0 * 2 + lh) ^ (lr & 7)) * 16),
        (uint32_t)(((wn * 4 + 1 * 2 + lh) ^ (lr & 7)) * 16) };

    auto load_frags = [&](int buf, int st_idx, int ks) {
        const uint32_t st = sbase + st_idx * STG_SZ;
        uint32_t aaddr = st + a_row_off + a_chunk[ks];
        LDSM_X4(ahf[buf][0], aaddr);
        LDSM_X4(ahf[buf][1], aaddr + 1024);            // +16 rows * 64B
        LDSM_X4(alf[buf][0], aaddr + STG_ALO);
        LDSM_X4(alf[buf][1], aaddr + STG_ALO + 1024);
        uint32_t bbase = st + STG_BHI + (uint32_t)(ks * 2048) + b_row_off;
#pragma unroll
        for (int np = 0; np < 2; np++) {
            uint32_t baddr = bbase + b_chunk[np];
            LDSM_X4T(&bhf[buf][np * 4], baddr);
            LDSM_X4T(&blf[buf][np * 4], baddr + (STG_BLO - STG_BHI));
        }
    };

    auto mma_all = [&](int buf) {
#pragma unroll
        for (int ni = 0; ni < 4; ni++) {
            MMA_BF16(acc[0][ni], alf[buf][0], bhf[buf][ni * 2], bhf[buf][ni * 2 + 1]);
            MMA_BF16(acc[1][ni], alf[buf][1], bhf[buf][ni * 2], bhf[buf][ni * 2 + 1]);
        }
#pragma unroll
        for (int ni = 0; ni < 4; ni++) {
            MMA_BF16(acc[0][ni], ahf[buf][0], blf[buf][ni * 2], blf[buf][ni * 2 + 1]);
            MMA_BF16(acc[1][ni], ahf[buf][1], blf[buf][ni * 2], blf[buf][ni * 2 + 1]);
        }
#pragma unroll
        for (int ni = 0; ni < 4; ni++) {
            MMA_BF16(acc[0][ni], ahf[buf][0], bhf[buf][ni * 2], bhf[buf][ni * 2 + 1]);
            MMA_BF16(acc[1][ni], ahf[buf][1], bhf[buf][ni * 2], bhf[buf][ni * 2 + 1]);
        }
    };

    load_stage(0, sbase,              okt0_0, okt0_1); cp_commit();
    load_stage(1, sbase + STG_SZ,     okt0_0, okt0_1); cp_commit();
    load_stage(2, sbase + 2 * STG_SZ, okt0_0, okt0_1); cp_commit();
    cp_wait<1>();
    __syncthreads();
    load_frags(0, 0, 0);

    for (int base = 0; base < NKt; base += 4) {
#pragma unroll
        for (int u = 0; u < 4; u++) {
            const int kt = base + u;
            if (kt > 0) {
                cp_wait<1>();
                __syncthreads();
            }
            load_frags(1, u, 1);
            mma_all(0);
            if (kt + 3 < NKt) {
                const int k3 = kt + 3;
                const int tap = (k3 >= KTT) + (k3 >= 2 * KTT);
                const int oa0 = (tap == 1) ? 1
                              : ((tap == 0) ? okt0_0 : okt2_0);
                const int oa1 = (tap == 1) ? 1
                              : ((tap == 0) ? okt0_1 : okt2_1);
                load_stage(k3, sbase + (((u + 3) & 3) * STG_SZ), oa0, oa1);
            }
            cp_commit();
            if (kt + 1 < NKt) load_frags(0, (u + 1) & 3, 0);
            mma_all(1);
        }
    }

    // ---- epilogue: bias + activation (per-column act select) ----
    const int  dircol = (col0 >= 3072) ? 1 : 0;
    const float* bias = dircol ? biasR : biasF;
    const int  lcol0  = col0 - dircol * 3072;

#pragma unroll
    for (int mi = 0; mi < 2; mi++) {
        int r0g = row0 + wm * 32 + mi * 16 + gp;
#pragma unroll
        for (int ni = 0; ni < 4; ni++) {
            int cl  = lcol0 + wn * 32 + ni * 8 + tg * 2;
            int cg  = col0  + wn * 32 + ni * 8 + tg * 2;
            const bool ztan = (cl >= 2048);
            float b0v = bias[cl], b1v = bias[cl + 1];
            float v[4] = { acc[mi][ni][0] + b0v, acc[mi][ni][1] + b1v,
                           acc[mi][ni][2] + b0v, acc[mi][ni][3] + b1v };
#pragma unroll
            for (int j = 0; j < 4; j++) {
                if (ztan) v[j] = 1.f - __fdividef(2.f, __expf(2.f * v[j]) + 1.f);
                else      v[j] = __fdividef(1.f, 1.f + __expf(-v[j]));
            }
            *(float2*)(gates + (size_t)r0g * NG + cg)       = make_float2(v[0], v[1]);
            *(float2*)(gates + (size_t)(r0g + 8) * NG + cg) = make_float2(v[2], v[3]);
        }
    }
}

// ---------------------------------------------------------------------------
// Chunked parallel fo-pool scan.
// Phase 1: per (dir, chunk, b, h) compute A = prod(f), B = scan(c_in=0).
// grid (32, 2, 16) x 256 -> 262K threads (bandwidth-bound, not latency).
// ---------------------------------------------------------------------------
__global__ void scan_chunk(const float* __restrict__ gates,
                           float* __restrict__ scA, float* __restrict__ scB)
{
    const int dir = blockIdx.y, ck = blockIdx.z;
    const int gid = blockIdx.x * blockDim.x + threadIdx.x;   // 0..8191
    const int b = gid >> 10, h = gid & 1023;
    const float* gb = gates + (size_t)b * Tlen * NG + dir * 3072 + h;

    float A = 1.f, c = 0.f;
    if (dir == 0) {
        const int tc = ck * CKL;
        for (int tt = 0; tt < CKL; tt += 8) {
            float fv[8], zv[8];
#pragma unroll
            for (int i = 0; i < 8; i++) {
                size_t o_ = (size_t)(tc + tt + i) * NG;
                fv[i] = gb[o_]; zv[i] = gb[o_ + 2048];
            }
#pragma unroll
            for (int i = 0; i < 8; i++) {
                A *= fv[i];
                c = fmaf(fv[i], c - zv[i], zv[i]);
            }
        }
    } else {
        const int tc = Tlen - 1 - ck * CKL;
        for (int tt = 0; tt < CKL; tt += 8) {
            float fv[8], zv[8];
#pragma unroll
            for (int i = 0; i < 8; i++) {
                size_t o_ = (size_t)(tc - tt - i) * NG;
                fv[i] = gb[o_]; zv[i] = gb[o_ + 2048];
            }
#pragma unroll
            for (int i = 0; i < 8; i++) {
                A *= fv[i];
                c = fmaf(fv[i], c - zv[i], zv[i]);
            }
        }
    }
    const int idx = (dir * NCK + ck) * 8192 + gid;
    scA[idx] = A;
    scB[idx] = c;
}

// ---------------------------------------------------------------------------
// Phase 2: fold upstream chunk (A,B) pairs into c_in, re-scan chunk, emit.
// fwd chunk NCK-1 owns last_h/last_c; rev chunk 0 owns t=Tlen-1 (first step).
// ---------------------------------------------------------------------------
template <bool L0>
__global__ void scan_emit(const float* __restrict__ gates,
                          float* __restrict__ out_f32,
                          __nv_bfloat16* __restrict__ ohi,
                          __nv_bfloat16* __restrict__ olo,
                          float* __restrict__ hid,
                          float* __restrict__ cel,
                          const float* __restrict__ scA,
                          const float* __restrict__ scB)
{
    const int dir = blockIdx.y, ck = blockIdx.z;
    const int gid = blockIdx.x * blockDim.x + threadIdx.x;   // 0..8191
    const int b = gid >> 10, h = gid & 1023;
    const float* gb = gates + (size_t)b * Tlen * NG + dir * 3072 + h;
    const size_t obase = (size_t)b * Tlen * 2048 + dir * 1024 + h;

    // fold upstream chunks (scan order) into incoming cell state
    float c = 0.f;
    for (int j = 0; j < ck; j++) {
        const int idx = (dir * NCK + j) * 8192 + gid;
        c = fmaf(scA[idx], c, scB[idx]);
    }

    auto emit = [&](int t, float hv) {
        size_t idx = obase + (size_t)t * 2048;
        if (L0) {
            __nv_bfloat16 hh = __float2bfloat16(hv);
            ohi[idx] = hh;
            olo[idx] = __float2bfloat16(hv - __bfloat162float(hh));
        } else {
            out_f32[idx] = hv;
        }
    };

    if (dir == 0) {
        const int tc = ck * CKL;
        float hl = 0.f;
        for (int tt = 0; tt < CKL; tt += 8) {
            float fv[8], ov[8], zv[8];
#pragma unroll
            for (int i = 0; i < 8; i++) {
                size_t o_ = (size_t)(tc + tt + i) * NG;
                fv[i] = gb[o_]; ov[i] = gb[o_ + 1024]; zv[i] = gb[o_ + 2048];
            }
#pragma unroll
            for (int i = 0; i < 8; i++) {
                c = fmaf(fv[i], c - zv[i], zv[i]);
                hl = c * ov[i];
                emit(tc + tt + i, hl);
            }
        }
        if (ck == NCK - 1) {
            hid[b * 2048 + h] = hl;
            cel[b * 2048 + h] = c;
        }
    } else {
        const int tc = Tlen - 1 - ck * CKL;
        float cfirst = 0.f, hfirst = 0.f;
        for (int tt = 0; tt < CKL; tt += 8) {
            float fv[8], ov[8], zv[8];
#pragma unroll
            for (int i = 0; i < 8; i++) {
                size_t o_ = (size_t)(tc - tt - i) * NG;
                fv[i] = gb[o_]; ov[i] = gb[o_ + 1024]; zv[i] = gb[o_ + 2048];
            }
#pragma unroll
            for (int i = 0; i < 8; i++) {
                c = fmaf(fv[i], c - zv[i], zv[i]);
                float hv = c * ov[i];
                emit(tc - tt - i, hv);
                if (tt + i == 0) { cfirst = c; hfirst = hv; }
            }
        }
        if (ck == 0) {
            hid[1024 + b * 2048 + h] = hfirst;
            cel[1024 + b * 2048 + h] = cfirst;
        }
    }
}

// ---------------------------------------------------------------------------
extern "C" void kernel_launch(void* const* d_in, const int* in_sizes, int n_in,
                              void* d_out, int out_size)
{
    const float* x   = (const float*)d_in[0];
    const float* w0f = (const float*)d_in[2];
    const float* b0f = (const float*)d_in[3];
    const float* w0r = (const float*)d_in[4];
    const float* b0r = (const float*)d_in[5];
    const float* w1f = (const float*)d_in[6];
    const float* b1f = (const float*)d_in[7];
    const float* w1r = (const float*)d_in[8];
    const float* b1r = (const float*)d_in[9];

    float* out1 = (float*)d_out;                         // [B,T,2H]
    float* hid  = out1 + (size_t)Bsz * Tlen * 2 * Hd;    // [4,B,H]
    float* cel  = hid + 4 * Bsz * Hd;

    float *gates, *scA, *scB;
    __nv_bfloat16 *xhi, *xlo, *o0hi, *o0lo, *wbhi, *wblo;
    cudaGetSymbolAddress((void**)&gates, g_gates);
    cudaGetSymbolAddress((void**)&xhi,  g_xhi);
    cudaGetSymbolAddress((void**)&xlo,  g_xlo);
    cudaGetSymbolAddress((void**)&o0hi, g_o0hi);
    cudaGetSymbolAddress((void**)&o0lo, g_o0lo);
    cudaGetSymbolAddress((void**)&wbhi, g_wbhi);
    cudaGetSymbolAddress((void**)&wblo, g_wblo);
    cudaGetSymbolAddress((void**)&scA,  g_scA);
    cudaGetSymbolAddress((void**)&scB,  g_scB);

    cudaFuncSetAttribute(conv_gemm<1024>,
                         cudaFuncAttributeMaxDynamicSharedMemorySize, SMEM_TOTAL);
    cudaFuncSetAttribute(conv_gemm<2048>,
                         cudaFuncAttributeMaxDynamicSharedMemorySize, SMEM_TOTAL);

    const dim3 sgrid(32, 2, NCK);

    // ---- layer 0 ----
    prep_x<<<8192, 256>>>((const float4*)x, (uint32_t*)xhi, (uint32_t*)xlo);
    prep_w<<<dim3(32, 96), 256>>>(w0f, wbhi, wblo, 1024, 0);
    prep_w<<<dim3(32, 96), 256>>>(w0r, wbhi, wblo, 1024, 3072);
    conv_gemm<1024><<<dim3(96, 64), 256, SMEM_TOTAL>>>(xhi, xlo, wbhi, wblo,
                                                       b0f, b0r, gates);
    scan_chunk<<<sgrid, 256>>>(gates, scA, scB);
    scan_emit<true><<<sgrid, 256>>>(gates, nullptr, o0hi, o0lo, hid, cel,
                                    scA, scB);
    // ---- layer 1 ----
    prep_w<<<dim3(64, 96), 256>>>(w1f, wbhi, wblo, 2048, 0);
    prep_w<<<dim3(64, 96), 256>>>(w1r, wbhi, wblo, 2048, 3072);
    conv_gemm<2048><<<dim3(96, 64), 256, SMEM_TOTAL>>>(o0hi, o0lo, wbhi, wblo,
                                                       b1f, b1r, gates);
    scan_chunk<<<sgrid, 256>>>(gates, scA, scB);
    scan_emit<false><<<sgrid, 256>>>(gates, out1, nullptr, nullptr,
                                     hid + 16384, cel + 16384, scA, scB);
}

// round 15
// speedup vs baseline: 1.1059x; 1.0043x over previous
#include <cuda_runtime.h>
#include <cuda_bf16.h>
#include <cuda_fp16.h>
#include <cstdint>

#define Bsz  8
#define Tlen 1024
#define Hd   1024
#define NG   6144   // fused fwd+rev gate width: [f|o|z]fwd [f|o|z]rev
#define NCK  16     // scan chunks per sequence
#define CKL  64     // chunk length

// ---------------- device scratch (no allocation allowed) -------------------
__device__ __half         g_gates[(size_t)Bsz * Tlen * NG];        // 100 MB
__device__ __nv_bfloat16  g_xhi [(size_t)Bsz * Tlen * 1024];
__device__ __nv_bfloat16  g_xlo [(size_t)Bsz * Tlen * 1024];
__device__ __nv_bfloat16  g_o0hi[(size_t)Bsz * Tlen * 2048];
__device__ __nv_bfloat16  g_o0lo[(size_t)Bsz * Tlen * 2048];
__device__ __nv_bfloat16  g_wbhi[(size_t)6144 * NG];   // k-major bf16 [3C][6144]
__device__ __nv_bfloat16  g_wblo[(size_t)6144 * NG];
__device__ float          g_scA[2 * NCK * 8192];       // chunk products
__device__ float          g_scB[2 * NCK * 8192];       // chunk offsets

// ---------------------------------------------------------------------------
__device__ __forceinline__ void split2(float a, float b, uint32_t& hp, uint32_t& lp)
{
    __nv_bfloat16 ha = __float2bfloat16(a), hb = __float2bfloat16(b);
    float la = a - __bfloat162float(ha);
    float lb = b - __bfloat162float(hb);
    __nv_bfloat162 hv; hv.x = ha; hv.y = hb;
    __nv_bfloat162 lv; lv.x = __float2bfloat16(la); lv.y = __float2bfloat16(lb);
    hp = *(uint32_t*)&hv; lp = *(uint32_t*)&lv;
}

__global__ void prep_x(const float4* __restrict__ x,
                       uint32_t* __restrict__ hi, uint32_t* __restrict__ lo)
{
    int i = blockIdx.x * blockDim.x + threadIdx.x;
    float4 v = x[i];
    uint32_t h0, l0, h1, l1;
    split2(v.x, v.y, h0, l0);
    split2(v.z, v.w, h1, l1);
    ((uint2*)hi)[i] = make_uint2(h0, h1);
    ((uint2*)lo)[i] = make_uint2(l0, l1);
}

// weight prep: w [3072, C, 3] fp32 -> hi/lo bf16 planes [3C][6144], k-major
__global__ void prep_w(const float* __restrict__ w,
                       __nv_bfloat16* __restrict__ wbhi,
                       __nv_bfloat16* __restrict__ wblo,
                       int C, int colbase)
{
    __shared__ float sm[32][97];
    const int tid = threadIdx.x;
    const int cb = blockIdx.x;
    const int jb = blockIdx.y;

    for (int i = tid; i < 32 * 96; i += 256) {
        int j = i / 96, q = i % 96;
        sm[j][q] = w[(size_t)(jb * 32 + j) * 3 * C + cb * 96 + q];
    }
    __syncthreads();

    for (int i = tid; i < 1536; i += 256) {
        int jp = i & 15;
        int tap = (i >> 4) % 3;
        int cl  = i / 48;
        int q   = cl * 3 + tap;
        uint32_t hp, lp;
        split2(sm[jp * 2][q], sm[jp * 2 + 1][q], hp, lp);
        size_t r = (size_t)tap * C + cb * 32 + cl;
        size_t off = r * NG + colbase + jb * 32 + jp * 2;
        *(uint32_t*)&wbhi[off] = hp;
        *(uint32_t*)&wblo[off] = lp;
    }
}

// ---------------------------------------------------------------------------
__device__ __forceinline__ void cp_async16(uint32_t smem, const void* gmem, int bytes)
{
    asm volatile("cp.async.cg.shared.global [%0], [%1], 16, %2;\n"
                 :: "r"(smem), "l"(gmem), "r"(bytes));
}
__device__ __forceinline__ void cp_commit()
{
    asm volatile("cp.async.commit_group;\n" ::: "memory");
}
template <int N>
__device__ __forceinline__ void cp_wait()
{
    asm volatile("cp.async.wait_group %0;\n" :: "n"(N) : "memory");
}

#define MMA_BF16(acc, a, b0, b1)                                              \
    asm volatile("mma.sync.aligned.m16n8k16.row.col.f32.bf16.bf16.f32 "       \
                 "{%0,%1,%2,%3}, {%4,%5,%6,%7}, {%8,%9}, {%0,%1,%2,%3};\n"    \
                 : "+f"(acc[0]), "+f"(acc[1]), "+f"(acc[2]), "+f"(acc[3])     \
                 : "r"(a[0]), "r"(a[1]), "r"(a[2]), "r"(a[3]),                \
                   "r"(b0), "r"(b1));

#define LDSM_X4(r, addr)                                                      \
    asm volatile("ldmatrix.sync.aligned.m8n8.x4.shared.b16 "                  \
                 "{%0,%1,%2,%3}, [%4];"                                       \
                 : "=r"((r)[0]), "=r"((r)[1]), "=r"((r)[2]), "=r"((r)[3])     \
                 : "r"(addr));

#define LDSM_X4T(r, addr)                                                     \
    asm volatile("ldmatrix.sync.aligned.m8n8.x4.trans.shared.b16 "            \
                 "{%0,%1,%2,%3}, [%4];"                                       \
                 : "=r"((r)[0]), "=r"((r)[1]), "=r"((r)[2]), "=r"((r)[3])     \
                 : "r"(addr));

// ---------------------------------------------------------------------------
// bf16x3 conv-as-GEMM — round-12 champion mainloop (tensor 84%):
// BM=128 BN=64, 256 threads (4m x 2n warps, warp tile 32x32), 2 CTAs/SM.
// 4-stage cp.async ring, register fragment double buffering,
// tap-independent linear A addressing, 4x-unrolled kt loop.
// Epilogue now emits fp16 gates (halves gate DRAM traffic).
// Swizzles: A chunk ^ ((row>>1)&3), B chunk ^ (row&7).
// ---------------------------------------------------------------------------
// stage layout (bytes): Ahi 8192 | Alo 8192 | Bhi 4096 | Blo 4096 = 24576
#define STG_SZ   24576
#define STG_ALO  8192
#define STG_BHI  16384
#define STG_BLO  20480
#define SMEM_TOTAL (4 * STG_SZ)

template <int C>
__global__ void __launch_bounds__(256, 2) conv_gemm(
    const __nv_bfloat16* __restrict__ Ahi,
    const __nv_bfloat16* __restrict__ Alo,
    const __nv_bfloat16* __restrict__ Bhi_,
    const __nv_bfloat16* __restrict__ Blo_,
    const float* __restrict__ biasF,
    const float* __restrict__ biasR,
    __half* __restrict__ gates)
{
    extern __shared__ char smraw[];

    const int tid  = threadIdx.x;          // 0..255
    const int lane = tid & 31;
    const int warp = tid >> 5;             // 0..7
    const int wm   = warp & 3;             // M
    const int wn   = warp >> 2;            // N (0..1)
    const int gp   = lane >> 2;
    const int tg   = lane & 3;
    const int lr   = lane & 15;
    const int lh   = lane >> 4;

    const int row0 = blockIdx.y << 7;
    const int col0 = blockIdx.x << 6;      // BN=64
    const int t0   = row0 & (Tlen - 1);
    const __nv_bfloat16* Ahb = Ahi + (size_t)(row0 - t0) * C;

    constexpr int KTT = C / 32;            // k-tiles per tap
    const int NKt = 3 * KTT;

    float acc[2][4][4];
#pragma unroll
    for (int a = 0; a < 2; a++)
#pragma unroll
        for (int b = 0; b < 4; b++)
#pragma unroll
            for (int c = 0; c < 4; c++) acc[a][b][c] = 0.f;

    uint32_t sbase;
    asm("{ .reg .u64 t; cvta.to.shared.u64 t, %1; cvt.u32.u64 %0, t; }"
        : "=r"(sbase) : "l"(smraw));

    const ptrdiff_t dALo = Alo - Ahi;      // plane delta (uniform)
    const ptrdiff_t dBLo = Blo_ - Bhi_;
    const int tt0 = t0 + (tid >> 2);           // r=0 row
    const int tt1 = tt0 + 64;                  // r=1 row
    const int okt0_0 = (tt0 > 0),    okt0_1 = (tt1 > 0);
    const int okt2_0 = (tt0 < 1023), okt2_1 = (tt1 < 1023);

    auto load_stage = [&](int kt, uint32_t stb, int oa0, int oa1) {
#pragma unroll
        for (int r = 0; r < 2; r++) {
            int idx = tid + (r << 8);
            int row = idx >> 2, c = idx & 3;
            int ok  = r ? oa1 : oa0;
            const __nv_bfloat16* src =
                Ahb + (size_t)(t0 + row - 1) * C + (size_t)kt * 32 + c * 8;
            if (!ok) src = Ahb;            // any valid address; bytes=0
            uint32_t dst = stb + (uint32_t)(row * 64 +
                                            (c ^ ((row >> 1) & 3)) * 16);
            cp_async16(dst,           src,        ok ? 16 : 0);
            cp_async16(dst + STG_ALO, src + dALo, ok ? 16 : 0);
        }
        {
            int rowb = tid >> 3, cb = tid & 7;
            const __nv_bfloat16* bs =
                Bhi_ + (size_t)(kt * 32 + rowb) * NG + col0 + cb * 8;
            uint32_t dst = stb + STG_BHI +
                           (uint32_t)(rowb * 128 + (cb ^ (rowb & 7)) * 16);
            cp_async16(dst,                       bs,        16);
            cp_async16(dst + (STG_BLO - STG_BHI), bs + dBLo, 16);
        }
    };

    uint32_t ahf[2][2][4], alf[2][2][4], bhf[2][8], blf[2][8];

    const uint32_t a_row_off  = (uint32_t)((wm * 32 + lr) * 64);
    const uint32_t a_chunk[2] = {
        (uint32_t)(((0 * 2 + lh) ^ ((lr >> 1) & 3)) * 16),
        (uint32_t)(((1 * 2 + lh) ^ ((lr >> 1) & 3)) * 16) };
    const uint32_t b_row_off  = (uint32_t)(lr * 128);
    const uint32_t b_chunk[2] = {
        (uint32_t)(((wn * 4 + 0 * 2 + lh) ^ (lr & 7)) * 16),
        (uint32_t)(((wn * 4 + 1 * 2 + lh) ^ (lr & 7)) * 16) };

    auto load_frags = [&](int buf, int st_idx, int ks) {
        const uint32_t st = sbase + st_idx * STG_SZ;
        uint32_t aaddr = st + a_row_off + a_chunk[ks];
        LDSM_X4(ahf[buf][0], aaddr);
        LDSM_X4(ahf[buf][1], aaddr + 1024);            // +16 rows * 64B
        LDSM_X4(alf[buf][0], aaddr + STG_ALO);
        LDSM_X4(alf[buf][1], aaddr + STG_ALO + 1024);
        uint32_t bbase = st + STG_BHI + (uint32_t)(ks * 2048) + b_row_off;
#pragma unroll
        for (int np = 0; np < 2; np++) {
            uint32_t baddr = bbase + b_chunk[np];
            LDSM_X4T(&bhf[buf][np * 4], baddr);
            LDSM_X4T(&blf[buf][np * 4], baddr + (STG_BLO - STG_BHI));
        }
    };

    auto mma_all = [&](int buf) {
#pragma unroll
        for (int ni = 0; ni < 4; ni++) {
            MMA_BF16(acc[0][ni], alf[buf][0], bhf[buf][ni * 2], bhf[buf][ni * 2 + 1]);
            MMA_BF16(acc[1][ni], alf[buf][1], bhf[buf][ni * 2], bhf[buf][ni * 2 + 1]);
        }
#pragma unroll
        for (int ni = 0; ni < 4; ni++) {
            MMA_BF16(acc[0][ni], ahf[buf][0], blf[buf][ni * 2], blf[buf][ni * 2 + 1]);
            MMA_BF16(acc[1][ni], ahf[buf][1], blf[buf][ni * 2], blf[buf][ni * 2 + 1]);
        }
#pragma unroll
        for (int ni = 0; ni < 4; ni++) {
            MMA_BF16(acc[0][ni], ahf[buf][0], bhf[buf][ni * 2], bhf[buf][ni * 2 + 1]);
            MMA_BF16(acc[1][ni], ahf[buf][1], bhf[buf][ni * 2], bhf[buf][ni * 2 + 1]);
        }
    };

    load_stage(0, sbase,              okt0_0, okt0_1); cp_commit();
    load_stage(1, sbase + STG_SZ,     okt0_0, okt0_1); cp_commit();
    load_stage(2, sbase + 2 * STG_SZ, okt0_0, okt0_1); cp_commit();
    cp_wait<1>();
    __syncthreads();
    load_frags(0, 0, 0);

    for (int base = 0; base < NKt; base += 4) {
#pragma unroll
        for (int u = 0; u < 4; u++) {
            const int kt = base + u;
            if (kt > 0) {
                cp_wait<1>();
                __syncthreads();
            }
            load_frags(1, u, 1);
            mma_all(0);
            if (kt + 3 < NKt) {
                const int k3 = kt + 3;
                const int tap = (k3 >= KTT) + (k3 >= 2 * KTT);
                const int oa0 = (tap == 1) ? 1
                              : ((tap == 0) ? okt0_0 : okt2_0);
                const int oa1 = (tap == 1) ? 1
                              : ((tap == 0) ? okt0_1 : okt2_1);
                load_stage(k3, sbase + (((u + 3) & 3) * STG_SZ), oa0, oa1);
            }
            cp_commit();
            if (kt + 1 < NKt) load_frags(0, (u + 1) & 3, 0);
            mma_all(1);
        }
    }

    // ---- epilogue: bias + activation -> fp16 gates ----
    const int  dircol = (col0 >= 3072) ? 1 : 0;
    const float* bias = dircol ? biasR : biasF;
    const int  lcol0  = col0 - dircol * 3072;

#pragma unroll
    for (int mi = 0; mi < 2; mi++) {
        int r0g = row0 + wm * 32 + mi * 16 + gp;
#pragma unroll
        for (int ni = 0; ni < 4; ni++) {
            int cl  = lcol0 + wn * 32 + ni * 8 + tg * 2;
            int cg  = col0  + wn * 32 + ni * 8 + tg * 2;
            const bool ztan = (cl >= 2048);
            float b0v = bias[cl], b1v = bias[cl + 1];
            float v[4] = { acc[mi][ni][0] + b0v, acc[mi][ni][1] + b1v,
                           acc[mi][ni][2] + b0v, acc[mi][ni][3] + b1v };
#pragma unroll
            for (int j = 0; j < 4; j++) {
                if (ztan) v[j] = 1.f - __fdividef(2.f, __expf(2.f * v[j]) + 1.f);
                else      v[j] = __fdividef(1.f, 1.f + __expf(-v[j]));
            }
            *(__half2*)(gates + (size_t)r0g * NG + cg) =
                __floats2half2_rn(v[0], v[1]);
            *(__half2*)(gates + (size_t)(r0g + 8) * NG + cg) =
                __floats2half2_rn(v[2], v[3]);
        }
    }
}

// ---------------------------------------------------------------------------
// Chunked parallel fo-pool scan (fp16 gates).
// Phase 1: per (dir, chunk, b, h) compute A = prod(f), B = scan(c_in=0).
// ---------------------------------------------------------------------------
__global__ void scan_chunk(const __half* __restrict__ gates,
                           float* __restrict__ scA, float* __restrict__ scB)
{
    const int dir = blockIdx.y, ck = blockIdx.z;
    const int gid = blockIdx.x * blockDim.x + threadIdx.x;   // 0..8191
    const int b = gid >> 10, h = gid & 1023;
    const __half* gb = gates + (size_t)b * Tlen * NG + dir * 3072 + h;

    float A = 1.f, c = 0.f;
    if (dir == 0) {
        const int tc = ck * CKL;
        for (int tt = 0; tt < CKL; tt += 8) {
            float fv[8], zv[8];
#pragma unroll
            for (int i = 0; i < 8; i++) {
                size_t o_ = (size_t)(tc + tt + i) * NG;
                fv[i] = __half2float(gb[o_]);
                zv[i] = __half2float(gb[o_ + 2048]);
            }
#pragma unroll
            for (int i = 0; i < 8; i++) {
                A *= fv[i];
                c = fmaf(fv[i], c - zv[i], zv[i]);
            }
        }
    } else {
        const int tc = Tlen - 1 - ck * CKL;
        for (int tt = 0; tt < CKL; tt += 8) {
            float fv[8], zv[8];
#pragma unroll
            for (int i = 0; i < 8; i++) {
                size_t o_ = (size_t)(tc - tt - i) * NG;
                fv[i] = __half2float(gb[o_]);
                zv[i] = __half2float(gb[o_ + 2048]);
            }
#pragma unroll
            for (int i = 0; i < 8; i++) {
                A *= fv[i];
                c = fmaf(fv[i], c - zv[i], zv[i]);
            }
        }
    }
    const int idx = (dir * NCK + ck) * 8192 + gid;
    scA[idx] = A;
    scB[idx] = c;
}

// ---------------------------------------------------------------------------
// Phase 2: fold upstream chunk (A,B) pairs into c_in, re-scan chunk, emit.
// fwd chunk NCK-1 owns last_h/last_c; rev chunk 0 owns t=Tlen-1 (first step).
// ---------------------------------------------------------------------------
template <bool L0>
__global__ void scan_emit(const __half* __restrict__ gates,
                          float* __restrict__ out_f32,
                          __nv_bfloat16* __restrict__ ohi,
                          __nv_bfloat16* __restrict__ olo,
                          float* __restrict__ hid,
                          float* __restrict__ cel,
                          const float* __restrict__ scA,
                          const float* __restrict__ scB)
{
    const int dir = blockIdx.y, ck = blockIdx.z;
    const int gid = blockIdx.x * blockDim.x + threadIdx.x;   // 0..8191
    const int b = gid >> 10, h = gid & 1023;
    const __half* gb = gates + (size_t)b * Tlen * NG + dir * 3072 + h;
    const size_t obase = (size_t)b * Tlen * 2048 + dir * 1024 + h;

    // fold upstream chunks (scan order) into incoming cell state
    float c = 0.f;
    for (int j = 0; j < ck; j++) {
        const int idx = (dir * NCK + j) * 8192 + gid;
        c = fmaf(scA[idx], c, scB[idx]);
    }

    auto emit = [&](int t, float hv) {
        size_t idx = obase + (size_t)t * 2048;
        if (L0) {
            __nv_bfloat16 hh = __float2bfloat16(hv);
            ohi[idx] = hh;
            olo[idx] = __float2bfloat16(hv - __bfloat162float(hh));
        } else {
            out_f32[idx] = hv;
        }
    };

    if (dir == 0) {
        const int tc = ck * CKL;
        float hl = 0.f;
        for (int tt = 0; tt < CKL; tt += 8) {
            float fv[8], ov[8], zv[8];
#pragma unroll
            for (int i = 0; i < 8; i++) {
                size_t o_ = (size_t)(tc + tt + i) * NG;
                fv[i] = __half2float(gb[o_]);
                ov[i] = __half2float(gb[o_ + 1024]);
                zv[i] = __half2float(gb[o_ + 2048]);
            }
#pragma unroll
            for (int i = 0; i < 8; i++) {
                c = fmaf(fv[i], c - zv[i], zv[i]);
                hl = c * ov[i];
                emit(tc + tt + i, hl);
            }
        }
        if (ck == NCK - 1) {
            hid[b * 2048 + h] = hl;
            cel[b * 2048 + h] = c;
        }
    } else {
        const int tc = Tlen - 1 - ck * CKL;
        float cfirst = 0.f, hfirst = 0.f;
        for (int tt = 0; tt < CKL; tt += 8) {
            float fv[8], ov[8], zv[8];
#pragma unroll
            for (int i = 0; i < 8; i++) {
                size_t o_ = (size_t)(tc - tt - i) * NG;
                fv[i] = __half2float(gb[o_]);
                ov[i] = __half2float(gb[o_ + 1024]);
                zv[i] = __half2float(gb[o_ + 2048]);
            }
#pragma unroll
            for (int i = 0; i < 8; i++) {
                c = fmaf(fv[i], c - zv[i], zv[i]);
                float hv = c * ov[i];
                emit(tc - tt - i, hv);
                if (tt + i == 0) { cfirst = c; hfirst = hv; }
            }
        }
        if (ck == 0) {
            hid[1024 + b * 2048 + h] = hfirst;
            cel[1024 + b * 2048 + h] = cfirst;
        }
    }
}

// ---------------------------------------------------------------------------
extern "C" void kernel_launch(void* const* d_in, const int* in_sizes, int n_in,
                              void* d_out, int out_size)
{
    const float* x   = (const float*)d_in[0];
    const float* w0f = (const float*)d_in[2];
    const float* b0f = (const float*)d_in[3];
    const float* w0r = (const float*)d_in[4];
    const float* b0r = (const float*)d_in[5];
    const float* w1f = (const float*)d_in[6];
    const float* b1f = (const float*)d_in[7];
    const float* w1r = (const float*)d_in[8];
    const float* b1r = (const float*)d_in[9];

    float* out1 = (float*)d_out;                         // [B,T,2H]
    float* hid  = out1 + (size_t)Bsz * Tlen * 2 * Hd;    // [4,B,H]
    float* cel  = hid + 4 * Bsz * Hd;

    float *scA, *scB;
    __half* gates;
    __nv_bfloat16 *xhi, *xlo, *o0hi, *o0lo, *wbhi, *wblo;
    cudaGetSymbolAddress((void**)&gates, g_gates);
    cudaGetSymbolAddress((void**)&xhi,  g_xhi);
    cudaGetSymbolAddress((void**)&xlo,  g_xlo);
    cudaGetSymbolAddress((void**)&o0hi, g_o0hi);
    cudaGetSymbolAddress((void**)&o0lo, g_o0lo);
    cudaGetSymbolAddress((void**)&wbhi, g_wbhi);
    cudaGetSymbolAddress((void**)&wblo, g_wblo);
    cudaGetSymbolAddress((void**)&scA,  g_scA);
    cudaGetSymbolAddress((void**)&scB,  g_scB);

    cudaFuncSetAttribute(conv_gemm<1024>,
                         cudaFuncAttributeMaxDynamicSharedMemorySize, SMEM_TOTAL);
    cudaFuncSetAttribute(conv_gemm<2048>,
                         cudaFuncAttributeMaxDynamicSharedMemorySize, SMEM_TOTAL);

    const dim3 sgrid(32, 2, NCK);

    // ---- layer 0 ----
    prep_x<<<8192, 256>>>((const float4*)x, (uint32_t*)xhi, (uint32_t*)xlo);
    prep_w<<<dim3(32, 96), 256>>>(w0f, wbhi, wblo, 1024, 0);
    prep_w<<<dim3(32, 96), 256>>>(w0r, wbhi, wblo, 1024, 3072);
    conv_gemm<1024><<<dim3(96, 64), 256, SMEM_TOTAL>>>(xhi, xlo, wbhi, wblo,
                                                       b0f, b0r, gates);
    scan_chunk<<<sgrid, 256>>>(gates, scA, scB);
    scan_emit<true><<<sgrid, 256>>>(gates, nullptr, o0hi, o0lo, hid, cel,
                                    scA, scB);
    // ---- layer 1 ----
    prep_w<<<dim3(64, 96), 256>>>(w1f, wbhi, wblo, 2048, 0);
    prep_w<<<dim3(64, 96), 256>>>(w1r, wbhi, wblo, 2048, 3072);
    conv_gemm<2048><<<dim3(96, 64), 256, SMEM_TOTAL>>>(o0hi, o0lo, wbhi, wblo,
                                                       b1f, b1r, gates);
    scan_chunk<<<sgrid, 256>>>(gates, scA, scB);
    scan_emit<false><<<sgrid, 256>>>(gates, out1, nullptr, nullptr,
                                     hid + 16384, cel + 16384, scA, scB);
}

// round 16
// speedup vs baseline: 1.1153x; 1.0085x over previous
#include <cuda_runtime.h>
#include <cuda_bf16.h>
#include <cuda_fp16.h>
#include <cstdint>

#define Bsz  8
#define Tlen 1024
#define Hd   1024
#define NG   6144   // fused fwd+rev gate width: [f|o|z]fwd [f|o|z]rev
#define NCK  16     // scan chunks per sequence
#define CKL  64     // chunk length

// ---------------- device scratch (no allocation allowed) -------------------
__device__ __half         g_gates[(size_t)Bsz * Tlen * NG];        // 100 MB
__device__ __nv_bfloat16  g_xhi [(size_t)Bsz * Tlen * 1024];
__device__ __nv_bfloat16  g_xlo [(size_t)Bsz * Tlen * 1024];
__device__ __nv_bfloat16  g_o0hi[(size_t)Bsz * Tlen * 2048];
__device__ __nv_bfloat16  g_o0lo[(size_t)Bsz * Tlen * 2048];
__device__ __nv_bfloat16  g_wbhi [(size_t)3072 * NG];  // L0 weights [3*1024][6144]
__device__ __nv_bfloat16  g_wblo [(size_t)3072 * NG];
__device__ __nv_bfloat16  g_wbhi1[(size_t)6144 * NG];  // L1 weights [3*2048][6144]
__device__ __nv_bfloat16  g_wblo1[(size_t)6144 * NG];
__device__ float          g_scA[2 * NCK * 8192];       // chunk products
__device__ float          g_scB[2 * NCK * 8192];       // chunk offsets

// ---- aux stream + events, created once at process init (host-side only) ---
static cudaStream_t g_s1;
static cudaEvent_t  g_evF, g_ev0, g_ev1;
namespace {
struct StreamInit {
    StreamInit() {
        cudaStreamCreateWithFlags(&g_s1, cudaStreamNonBlocking);
        cudaEventCreateWithFlags(&g_evF, cudaEventDisableTiming);
        cudaEventCreateWithFlags(&g_ev0, cudaEventDisableTiming);
        cudaEventCreateWithFlags(&g_ev1, cudaEventDisableTiming);
    }
} g_stream_init;
}

// ---------------------------------------------------------------------------
__device__ __forceinline__ void split2(float a, float b, uint32_t& hp, uint32_t& lp)
{
    __nv_bfloat16 ha = __float2bfloat16(a), hb = __float2bfloat16(b);
    float la = a - __bfloat162float(ha);
    float lb = b - __bfloat162float(hb);
    __nv_bfloat162 hv; hv.x = ha; hv.y = hb;
    __nv_bfloat162 lv; lv.x = __float2bfloat16(la); lv.y = __float2bfloat16(lb);
    hp = *(uint32_t*)&hv; lp = *(uint32_t*)&lv;
}

__global__ void prep_x(const float4* __restrict__ x,
                       uint32_t* __restrict__ hi, uint32_t* __restrict__ lo)
{
    int i = blockIdx.x * blockDim.x + threadIdx.x;
    float4 v = x[i];
    uint32_t h0, l0, h1, l1;
    split2(v.x, v.y, h0, l0);
    split2(v.z, v.w, h1, l1);
    ((uint2*)hi)[i] = make_uint2(h0, h1);
    ((uint2*)lo)[i] = make_uint2(l0, l1);
}

// weight prep: w [3072, C, 3] fp32 -> hi/lo bf16 planes [3C][6144], k-major
__global__ void prep_w(const float* __restrict__ w,
                       __nv_bfloat16* __restrict__ wbhi,
                       __nv_bfloat16* __restrict__ wblo,
                       int C, int colbase)
{
    __shared__ float sm[32][97];
    const int tid = threadIdx.x;
    const int cb = blockIdx.x;
    const int jb = blockIdx.y;

    for (int i = tid; i < 32 * 96; i += 256) {
        int j = i / 96, q = i % 96;
        sm[j][q] = w[(size_t)(jb * 32 + j) * 3 * C + cb * 96 + q];
    }
    __syncthreads();

    for (int i = tid; i < 1536; i += 256) {
        int jp = i & 15;
        int tap = (i >> 4) % 3;
        int cl  = i / 48;
        int q   = cl * 3 + tap;
        uint32_t hp, lp;
        split2(sm[jp * 2][q], sm[jp * 2 + 1][q], hp, lp);
        size_t r = (size_t)tap * C + cb * 32 + cl;
        size_t off = r * NG + colbase + jb * 32 + jp * 2;
        *(uint32_t*)&wbhi[off] = hp;
        *(uint32_t*)&wblo[off] = lp;
    }
}

// ---------------------------------------------------------------------------
__device__ __forceinline__ void cp_async16(uint32_t smem, const void* gmem, int bytes)
{
    asm volatile("cp.async.cg.shared.global [%0], [%1], 16, %2;\n"
                 :: "r"(smem), "l"(gmem), "r"(bytes));
}
__device__ __forceinline__ void cp_commit()
{
    asm volatile("cp.async.commit_group;\n" ::: "memory");
}
template <int N>
__device__ __forceinline__ void cp_wait()
{
    asm volatile("cp.async.wait_group %0;\n" :: "n"(N) : "memory");
}

#define MMA_BF16(acc, a, b0, b1)                                              \
    asm volatile("mma.sync.aligned.m16n8k16.row.col.f32.bf16.bf16.f32 "       \
                 "{%0,%1,%2,%3}, {%4,%5,%6,%7}, {%8,%9}, {%0,%1,%2,%3};\n"    \
                 : "+f"(acc[0]), "+f"(acc[1]), "+f"(acc[2]), "+f"(acc[3])     \
                 : "r"(a[0]), "r"(a[1]), "r"(a[2]), "r"(a[3]),                \
                   "r"(b0), "r"(b1));

#define LDSM_X4(r, addr)                                                      \
    asm volatile("ldmatrix.sync.aligned.m8n8.x4.shared.b16 "                  \
                 "{%0,%1,%2,%3}, [%4];"                                       \
                 : "=r"((r)[0]), "=r"((r)[1]), "=r"((r)[2]), "=r"((r)[3])     \
                 : "r"(addr));

#define LDSM_X4T(r, addr)                                                     \
    asm volatile("ldmatrix.sync.aligned.m8n8.x4.trans.shared.b16 "            \
                 "{%0,%1,%2,%3}, [%4];"                                       \
                 : "=r"((r)[0]), "=r"((r)[1]), "=r"((r)[2]), "=r"((r)[3])     \
                 : "r"(addr));

// ---------------------------------------------------------------------------
// bf16x3 conv-as-GEMM — round-12 champion mainloop (tensor 84%):
// BM=128 BN=64, 256 threads (4m x 2n warps, warp tile 32x32), 2 CTAs/SM.
// 4-stage cp.async ring, register fragment double buffering,
// tap-independent linear A addressing, 4x-unrolled kt loop.
// fp16 gate epilogue. Swizzles: A chunk ^ ((row>>1)&3), B chunk ^ (row&7).
// ---------------------------------------------------------------------------
// stage layout (bytes): Ahi 8192 | Alo 8192 | Bhi 4096 | Blo 4096 = 24576
#define STG_SZ   24576
#define STG_ALO  8192
#define STG_BHI  16384
#define STG_BLO  20480
#define SMEM_TOTAL (4 * STG_SZ)

template <int C>
__global__ void __launch_bounds__(256, 2) conv_gemm(
    const __nv_bfloat16* __restrict__ Ahi,
    const __nv_bfloat16* __restrict__ Alo,
    const __nv_bfloat16* __restrict__ Bhi_,
    const __nv_bfloat16* __restrict__ Blo_,
    const float* __restrict__ biasF,
    const float* __restrict__ biasR,
    __half* __restrict__ gates)
{
    extern __shared__ char smraw[];

    const int tid  = threadIdx.x;          // 0..255
    const int lane = tid & 31;
    const int warp = tid >> 5;             // 0..7
    const int wm   = warp & 3;             // M
    const int wn   = warp >> 2;            // N (0..1)
    const int gp   = lane >> 2;
    const int tg   = lane & 3;
    const int lr   = lane & 15;
    const int lh   = lane >> 4;

    const int row0 = blockIdx.y << 7;
    const int col0 = blockIdx.x << 6;      // BN=64
    const int t0   = row0 & (Tlen - 1);
    const __nv_bfloat16* Ahb = Ahi + (size_t)(row0 - t0) * C;

    constexpr int KTT = C / 32;            // k-tiles per tap
    const int NKt = 3 * KTT;

    float acc[2][4][4];
#pragma unroll
    for (int a = 0; a < 2; a++)
#pragma unroll
        for (int b = 0; b < 4; b++)
#pragma unroll
            for (int c = 0; c < 4; c++) acc[a][b][c] = 0.f;

    uint32_t sbase;
    asm("{ .reg .u64 t; cvta.to.shared.u64 t, %1; cvt.u32.u64 %0, t; }"
        : "=r"(sbase) : "l"(smraw));

    const ptrdiff_t dALo = Alo - Ahi;      // plane delta (uniform)
    const ptrdiff_t dBLo = Blo_ - Bhi_;
    const int tt0 = t0 + (tid >> 2);           // r=0 row
    const int tt1 = tt0 + 64;                  // r=1 row
    const int okt0_0 = (tt0 > 0),    okt0_1 = (tt1 > 0);
    const int okt2_0 = (tt0 < 1023), okt2_1 = (tt1 < 1023);

    auto load_stage = [&](int kt, uint32_t stb, int oa0, int oa1) {
#pragma unroll
        for (int r = 0; r < 2; r++) {
            int idx = tid + (r << 8);
            int row = idx >> 2, c = idx & 3;
            int ok  = r ? oa1 : oa0;
            const __nv_bfloat16* src =
                Ahb + (size_t)(t0 + row - 1) * C + (size_t)kt * 32 + c * 8;
            if (!ok) src = Ahb;            // any valid address; bytes=0
            uint32_t dst = stb + (uint32_t)(row * 64 +
                                            (c ^ ((row >> 1) & 3)) * 16);
            cp_async16(dst,           src,        ok ? 16 : 0);
            cp_async16(dst + STG_ALO, src + dALo, ok ? 16 : 0);
        }
        {
            int rowb = tid >> 3, cb = tid & 7;
            const __nv_bfloat16* bs =
                Bhi_ + (size_t)(kt * 32 + rowb) * NG + col0 + cb * 8;
            uint32_t dst = stb + STG_BHI +
                           (uint32_t)(rowb * 128 + (cb ^ (rowb & 7)) * 16);
            cp_async16(dst,                       bs,        16);
            cp_async16(dst + (STG_BLO - STG_BHI), bs + dBLo, 16);
        }
    };

    uint32_t ahf[2][2][4], alf[2][2][4], bhf[2][8], blf[2][8];

    const uint32_t a_row_off  = (uint32_t)((wm * 32 + lr) * 64);
    const uint32_t a_chunk[2] = {
        (uint32_t)(((0 * 2 + lh) ^ ((lr >> 1) & 3)) * 16),
        (uint32_t)(((1 * 2 + lh) ^ ((lr >> 1) & 3)) * 16) };
    const uint32_t b_row_off  = (uint32_t)(lr * 128);
    const uint32_t b_chunk[2] = {
        (uint32_t)(((wn * 4 + 0 * 2 + lh) ^ (lr & 7)) * 16),
        (uint32_t)(((wn * 4 + 1 * 2 + lh) ^ (lr & 7)) * 16) };

    auto load_frags = [&](int buf, int st_idx, int ks) {
        const uint32_t st = sbase + st_idx * STG_SZ;
        uint32_t aaddr = st + a_row_off + a_chunk[ks];
        LDSM_X4(ahf[buf][0], aaddr);
        LDSM_X4(ahf[buf][1], aaddr + 1024);            // +16 rows * 64B
        LDSM_X4(alf[buf][0], aaddr + STG_ALO);
        LDSM_X4(alf[buf][1], aaddr + STG_ALO + 1024);
        uint32_t bbase = st + STG_BHI + (uint32_t)(ks * 2048) + b_row_off;
#pragma unroll
        for (int np = 0; np < 2; np++) {
            uint32_t baddr = bbase + b_chunk[np];
            LDSM_X4T(&bhf[buf][np * 4], baddr);
            LDSM_X4T(&blf[buf][np * 4], baddr + (STG_BLO - STG_BHI));
        }
    };

    auto mma_all = [&](int buf) {
#pragma unroll
        for (int ni = 0; ni < 4; ni++) {
            MMA_BF16(acc[0][ni], alf[buf][0], bhf[buf][ni * 2], bhf[buf][ni * 2 + 1]);
            MMA_BF16(acc[1][ni], alf[buf][1], bhf[buf][ni * 2], bhf[buf][ni * 2 + 1]);
        }
#pragma unroll
        for (int ni = 0; ni < 4; ni++) {
            MMA_BF16(acc[0][ni], ahf[buf][0], blf[buf][ni * 2], blf[buf][ni * 2 + 1]);
            MMA_BF16(acc[1][ni], ahf[buf][1], blf[buf][ni * 2], blf[buf][ni * 2 + 1]);
        }
#pragma unroll
        for (int ni = 0; ni < 4; ni++) {
            MMA_BF16(acc[0][ni], ahf[buf][0], bhf[buf][ni * 2], bhf[buf][ni * 2 + 1]);
            MMA_BF16(acc[1][ni], ahf[buf][1], bhf[buf][ni * 2], bhf[buf][ni * 2 + 1]);
        }
    };

    load_stage(0, sbase,              okt0_0, okt0_1); cp_commit();
    load_stage(1, sbase + STG_SZ,     okt0_0, okt0_1); cp_commit();
    load_stage(2, sbase + 2 * STG_SZ, okt0_0, okt0_1); cp_commit();
    cp_wait<1>();
    __syncthreads();
    load_frags(0, 0, 0);

    for (int base = 0; base < NKt; base += 4) {
#pragma unroll
        for (int u = 0; u < 4; u++) {
            const int kt = base + u;
            if (kt > 0) {
                cp_wait<1>();
                __syncthreads();
            }
            load_frags(1, u, 1);
            mma_all(0);
            if (kt + 3 < NKt) {
                const int k3 = kt + 3;
                const int tap = (k3 >= KTT) + (k3 >= 2 * KTT);
                const int oa0 = (tap == 1) ? 1
                              : ((tap == 0) ? okt0_0 : okt2_0);
                const int oa1 = (tap == 1) ? 1
                              : ((tap == 0) ? okt0_1 : okt2_1);
                load_stage(k3, sbase + (((u + 3) & 3) * STG_SZ), oa0, oa1);
            }
            cp_commit();
            if (kt + 1 < NKt) load_frags(0, (u + 1) & 3, 0);
            mma_all(1);
        }
    }

    // ---- epilogue: bias + activation -> fp16 gates ----
    const int  dircol = (col0 >= 3072) ? 1 : 0;
    const float* bias = dircol ? biasR : biasF;
    const int  lcol0  = col0 - dircol * 3072;

#pragma unroll
    for (int mi = 0; mi < 2; mi++) {
        int r0g = row0 + wm * 32 + mi * 16 + gp;
#pragma unroll
        for (int ni = 0; ni < 4; ni++) {
            int cl  = lcol0 + wn * 32 + ni * 8 + tg * 2;
            int cg  = col0  + wn * 32 + ni * 8 + tg * 2;
            const bool ztan = (cl >= 2048);
            float b0v = bias[cl], b1v = bias[cl + 1];
            float v[4] = { acc[mi][ni][0] + b0v, acc[mi][ni][1] + b1v,
                           acc[mi][ni][2] + b0v, acc[mi][ni][3] + b1v };
#pragma unroll
            for (int j = 0; j < 4; j++) {
                if (ztan) v[j] = 1.f - __fdividef(2.f, __expf(2.f * v[j]) + 1.f);
                else      v[j] = __fdividef(1.f, 1.f + __expf(-v[j]));
            }
            *(__half2*)(gates + (size_t)r0g * NG + cg) =
                __floats2half2_rn(v[0], v[1]);
            *(__half2*)(gates + (size_t)(r0g + 8) * NG + cg) =
                __floats2half2_rn(v[2], v[3]);
        }
    }
}

// ---------------------------------------------------------------------------
// Chunked parallel fo-pool scan (fp16 gates).
// Phase 1: per (dir, chunk, b, h) compute A = prod(f), B = scan(c_in=0).
// ---------------------------------------------------------------------------
__global__ void scan_chunk(const __half* __restrict__ gates,
                           float* __restrict__ scA, float* __restrict__ scB)
{
    const int dir = blockIdx.y, ck = blockIdx.z;
    const int gid = blockIdx.x * blockDim.x + threadIdx.x;   // 0..8191
    const int b = gid >> 10, h = gid & 1023;
    const __half* gb = gates + (size_t)b * Tlen * NG + dir * 3072 + h;

    float A = 1.f, c = 0.f;
    if (dir == 0) {
        const int tc = ck * CKL;
        for (int tt = 0; tt < CKL; tt += 8) {
            float fv[8], zv[8];
#pragma unroll
            for (int i = 0; i < 8; i++) {
                size_t o_ = (size_t)(tc + tt + i) * NG;
                fv[i] = __half2float(gb[o_]);
                zv[i] = __half2float(gb[o_ + 2048]);
            }
#pragma unroll
            for (int i = 0; i < 8; i++) {
                A *= fv[i];
                c = fmaf(fv[i], c - zv[i], zv[i]);
            }
        }
    } else {
        const int tc = Tlen - 1 - ck * CKL;
        for (int tt = 0; tt < CKL; tt += 8) {
            float fv[8], zv[8];
#pragma unroll
            for (int i = 0; i < 8; i++) {
                size_t o_ = (size_t)(tc - tt - i) * NG;
                fv[i] = __half2float(gb[o_]);
                zv[i] = __half2float(gb[o_ + 2048]);
            }
#pragma unroll
            for (int i = 0; i < 8; i++) {
                A *= fv[i];
                c = fmaf(fv[i], c - zv[i], zv[i]);
            }
        }
    }
    const int idx = (dir * NCK + ck) * 8192 + gid;
    scA[idx] = A;
    scB[idx] = c;
}

// ---------------------------------------------------------------------------
// Phase 2: fold upstream chunk (A,B) pairs into c_in, re-scan chunk, emit.
// fwd chunk NCK-1 owns last_h/last_c; rev chunk 0 owns t=Tlen-1 (first step).
// ---------------------------------------------------------------------------
template <bool L0>
__global__ void scan_emit(const __half* __restrict__ gates,
                          float* __restrict__ out_f32,
                          __nv_bfloat16* __restrict__ ohi,
                          __nv_bfloat16* __restrict__ olo,
                          float* __restrict__ hid,
                          float* __restrict__ cel,
                          const float* __restrict__ scA,
                          const float* __restrict__ scB)
{
    const int dir = blockIdx.y, ck = blockIdx.z;
    const int gid = blockIdx.x * blockDim.x + threadIdx.x;   // 0..8191
    const int b = gid >> 10, h = gid & 1023;
    const __half* gb = gates + (size_t)b * Tlen * NG + dir * 3072 + h;
    const size_t obase = (size_t)b * Tlen * 2048 + dir * 1024 + h;

    // fold upstream chunks (scan order) into incoming cell state
    float c = 0.f;
    for (int j = 0; j < ck; j++) {
        const int idx = (dir * NCK + j) * 8192 + gid;
        c = fmaf(scA[idx], c, scB[idx]);
    }

    auto emit = [&](int t, float hv) {
        size_t idx = obase + (size_t)t * 2048;
        if (L0) {
            __nv_bfloat16 hh = __float2bfloat16(hv);
            ohi[idx] = hh;
            olo[idx] = __float2bfloat16(hv - __bfloat162float(hh));
        } else {
            out_f32[idx] = hv;
        }
    };

    if (dir == 0) {
        const int tc = ck * CKL;
        float hl = 0.f;
        for (int tt = 0; tt < CKL; tt += 8) {
            float fv[8], ov[8], zv[8];
#pragma unroll
            for (int i = 0; i < 8; i++) {
                size_t o_ = (size_t)(tc + tt + i) * NG;
                fv[i] = __half2float(gb[o_]);
                ov[i] = __half2float(gb[o_ + 1024]);
                zv[i] = __half2float(gb[o_ + 2048]);
            }
#pragma unroll
            for (int i = 0; i < 8; i++) {
                c = fmaf(fv[i], c - zv[i], zv[i]);
                hl = c * ov[i];
                emit(tc + tt + i, hl);
            }
        }
        if (ck == NCK - 1) {
            hid[b * 2048 + h] = hl;
            cel[b * 2048 + h] = c;
        }
    } else {
        const int tc = Tlen - 1 - ck * CKL;
        float cfirst = 0.f, hfirst = 0.f;
        for (int tt = 0; tt < CKL; tt += 8) {
            float fv[8], ov[8], zv[8];
#pragma unroll
            for (int i = 0; i < 8; i++) {
                size_t o_ = (size_t)(tc - tt - i) * NG;
                fv[i] = __half2float(gb[o_]);
                ov[i] = __half2float(gb[o_ + 1024]);
                zv[i] = __half2float(gb[o_ + 2048]);
            }
#pragma unroll
            for (int i = 0; i < 8; i++) {
                c = fmaf(fv[i], c - zv[i], zv[i]);
                float hv = c * ov[i];
                emit(tc - tt - i, hv);
                if (tt + i == 0) { cfirst = c; hfirst = hv; }
            }
        }
        if (ck == 0) {
            hid[1024 + b * 2048 + h] = hfirst;
            cel[1024 + b * 2048 + h] = cfirst;
        }
    }
}

// ---------------------------------------------------------------------------
extern "C" void kernel_launch(void* const* d_in, const int* in_sizes, int n_in,
                              void* d_out, int out_size)
{
    const float* x   = (const float*)d_in[0];
    const float* w0f = (const float*)d_in[2];
    const float* b0f = (const float*)d_in[3];
    const float* w0r = (const float*)d_in[4];
    const float* b0r = (const float*)d_in[5];
    const float* w1f = (const float*)d_in[6];
    const float* b1f = (const float*)d_in[7];
    const float* w1r = (const float*)d_in[8];
    const float* b1r = (const float*)d_in[9];

    float* out1 = (float*)d_out;                         // [B,T,2H]
    float* hid  = out1 + (size_t)Bsz * Tlen * 2 * Hd;    // [4,B,H]
    float* cel  = hid + 4 * Bsz * Hd;

    float *scA, *scB;
    __half* gates;
    __nv_bfloat16 *xhi, *xlo, *o0hi, *o0lo, *wbhi, *wblo, *wbhi1, *wblo1;
    cudaGetSymbolAddress((void**)&gates, g_gates);
    cudaGetSymbolAddress((void**)&xhi,   g_xhi);
    cudaGetSymbolAddress((void**)&xlo,   g_xlo);
    cudaGetSymbolAddress((void**)&o0hi,  g_o0hi);
    cudaGetSymbolAddress((void**)&o0lo,  g_o0lo);
    cudaGetSymbolAddress((void**)&wbhi,  g_wbhi);
    cudaGetSymbolAddress((void**)&wblo,  g_wblo);
    cudaGetSymbolAddress((void**)&wbhi1, g_wbhi1);
    cudaGetSymbolAddress((void**)&wblo1, g_wblo1);
    cudaGetSymbolAddress((void**)&scA,   g_scA);
    cudaGetSymbolAddress((void**)&scB,   g_scB);

    cudaFuncSetAttribute(conv_gemm<1024>,
                         cudaFuncAttributeMaxDynamicSharedMemorySize, SMEM_TOTAL);
    cudaFuncSetAttribute(conv_gemm<2048>,
                         cudaFuncAttributeMaxDynamicSharedMemorySize, SMEM_TOTAL);

    const dim3 sgrid(32, 2, NCK);

    // ---- fork aux stream: all 4 weight preps run off the critical path ----
    cudaEventRecord(g_evF, 0);
    cudaStreamWaitEvent(g_s1, g_evF, 0);
    prep_w<<<dim3(32, 96), 256, 0, g_s1>>>(w0f, wbhi,  wblo,  1024, 0);
    prep_w<<<dim3(32, 96), 256, 0, g_s1>>>(w0r, wbhi,  wblo,  1024, 3072);
    cudaEventRecord(g_ev0, g_s1);
    prep_w<<<dim3(64, 96), 256, 0, g_s1>>>(w1f, wbhi1, wblo1, 2048, 0);
    prep_w<<<dim3(64, 96), 256, 0, g_s1>>>(w1r, wbhi1, wblo1, 2048, 3072);
    cudaEventRecord(g_ev1, g_s1);

    // ---- main stream: layer 0 (prep_x overlaps L0 weight prep) ----
    prep_x<<<8192, 256>>>((const float4*)x, (uint32_t*)xhi, (uint32_t*)xlo);
    cudaStreamWaitEvent(0, g_ev0, 0);
    conv_gemm<1024><<<dim3(96, 64), 256, SMEM_TOTAL>>>(xhi, xlo, wbhi, wblo,
                                                       b0f, b0r, gates);
    scan_chunk<<<sgrid, 256>>>(gates, scA, scB);
    scan_emit<true><<<sgrid, 256>>>(gates, nullptr, o0hi, o0lo, hid, cel,
                                    scA, scB);
    // ---- layer 1 (weights prepped during L0 GEMM; join aux stream) ----
    cudaStreamWaitEvent(0, g_ev1, 0);
    conv_gemm<2048><<<dim3(96, 64), 256, SMEM_TOTAL>>>(o0hi, o0lo, wbhi1, wblo1,
                                                       b1f, b1r, gates);
    scan_chunk<<<sgrid, 256>>>(gates, scA, scB);
    scan_emit<false><<<sgrid, 256>>>(gates, out1, nullptr, nullptr,
                                     hid + 16384, cel + 16384, scA, scB);
}